// round 11
// baseline (speedup 1.0000x reference)
#include <cuda_runtime.h>
#include <cuda_bf16.h>
#include <cstdint>
#include <math.h>

// S4D as 1024 batched small GEMMs on mma.sync (HMMA, sm_80 baseline).
//
// K[h, 32k+j] = Re( sum_n cc_n * (r_n^32)^k * r_n^j ),  r_n = exp(dtA[h,n]).
// Per head:  D[128x32] = A[128 x 128] * B[32 x 128]^T   (bf16, fp32 accum)
//   A[k, 2n+0/1] = (Vr_hi, Vi_hi),  A[k, 64+2n+0/1] = (Vr_lo, Vi_lo),  V = r^(32k)
//   B[j, 2n+0/1] = (Ur_hi, -Ui_hi), B[j, 64+2n+0/1] = (Ur_lo, -Ui_lo), U = cc*r^j
// D = Ahi*Bhi + Ahi*Blo + Alo*Bhi (lo*lo dropped ~2^-18): 12 k16 MMA steps.
//
// R11: fragment reuse across split terms — per k16 chunk q, A_hi and B_hi
// fragments are loaded ONCE and reused (t0 uses ah*bh, t1 ah*bl, t2 al*bh):
// 32 LDSM/warp instead of 48, cutting the dominant L1 wavefront stream.

#define AST 136   // A row stride in halves (272B; LDSM conflict-free)
#define BST 136

__device__ __forceinline__ float2 cmul(float2 a, float2 b) {
    return make_float2(fmaf(a.x, b.x, -a.y * b.y), fmaf(a.x, b.y, a.y * b.x));
}
// hi = {bf16rn(x), bf16rn(y)}; lo = packed exact residuals
__device__ __forceinline__ void split_pack(float x, float y, uint32_t& hi, uint32_t& lo) {
    asm("cvt.rn.bf16x2.f32 %0, %1, %2;" : "=r"(hi) : "f"(y), "f"(x));
    uint32_t xh, yh;
    asm("prmt.b32 %0, %1, %2, 0x1054;" : "=r"(xh) : "r"(hi), "r"(0));
    asm("prmt.b32 %0, %1, %2, 0x3254;" : "=r"(yh) : "r"(hi), "r"(0));
    float xr = x - __uint_as_float(xh);
    float yr = y - __uint_as_float(yh);
    asm("cvt.rn.bf16x2.f32 %0, %1, %2;" : "=r"(lo) : "f"(yr), "f"(xr));
}
__device__ __forceinline__ uint32_t smem_u32(const void* p) {
    uint32_t a;
    asm("{ .reg .u64 t; cvta.to.shared.u64 t, %1; cvt.u32.u64 %0, t; }" : "=r"(a) : "l"(p));
    return a;
}
__device__ __forceinline__ void sts32(uint32_t addr, uint32_t v) {
    asm volatile("st.shared.b32 [%0], %1;" :: "r"(addr), "r"(v) : "memory");
}
__device__ __forceinline__ void ldsm4(uint32_t* r, uint32_t addr) {
    asm volatile("ldmatrix.sync.aligned.m8n8.x4.shared.b16 {%0,%1,%2,%3}, [%4];"
                 : "=r"(r[0]), "=r"(r[1]), "=r"(r[2]), "=r"(r[3]) : "r"(addr));
}
__device__ __forceinline__ void mma16816(float* c, const uint32_t* a,
                                         uint32_t b0, uint32_t b1) {
    asm("mma.sync.aligned.m16n8k16.row.col.f32.bf16.bf16.f32 "
        "{%0,%1,%2,%3}, {%4,%5,%6,%7}, {%8,%9}, {%0,%1,%2,%3};"
        : "+f"(c[0]), "+f"(c[1]), "+f"(c[2]), "+f"(c[3])
        : "r"(a[0]), "r"(a[1]), "r"(a[2]), "r"(a[3]), "r"(b0), "r"(b1));
}

__global__ void __launch_bounds__(128, 5)
s4d_mma(float* __restrict__ out,
        const float* __restrict__ C, const float* __restrict__ log_dt,
        const float* __restrict__ lAr, const float* __restrict__ Ai) {
    __shared__ __align__(16) __nv_bfloat16 sA[128 * AST];  // 34816 B
    __shared__ __align__(16) __nv_bfloat16 sB[32 * BST];   //  8704 B

    const int h    = blockIdx.x;
    const int tid  = threadIdx.x;
    const int wid  = tid >> 5;   // warp == A chunk == MMA row block
    const int lane = tid & 31;   // lane == mode n

    // ---- per-thread constants for mode n = lane (dup across warps) ----
    const int idx = h * 32 + lane;
    float dt = expf(log_dt[h]);
    float ar = -expf(lAr[idx]);
    float ai = Ai[idx];
    float x  = ar * dt, th = ai * dt;
    float sy, cy; sincosf(th, &sy, &cy);
    float ex = expf(x);
    float2 r = make_float2(ex * cy, ex * sy);
    float den  = ar * ar + ai * ai;
    float c2   = 2.0f * C[idx] / den;
    float2 cc  = make_float2(c2 * ((r.x - 1.0f) * ar + r.y * ai),
                             c2 * (r.y * ar - (r.x - 1.0f) * ai));

    // power ladder
    float2 r2  = cmul(r, r),   r4  = cmul(r2, r2);
    float2 r8  = cmul(r4, r4), r16 = cmul(r8, r8);
    float2 R   = cmul(r16, r16);                 // r^32

    // ---- B march first: U[j] = cc * r^j, rows j in [8*wid, 8*wid+8) ----
    {
        float2 u0 = cc;
        if (wid & 1) u0 = cmul(u0, r8);
        if (wid & 2) u0 = cmul(u0, r16);
        float2 u1 = cmul(u0, r);
        uint32_t w = smem_u32(sB) + (8 * wid) * (BST * 2) + 4 * lane;
        #pragma unroll
        for (int it = 0; it < 4; ++it) {
            uint32_t hi, lo;
            split_pack(u0.x, -u0.y, hi, lo);
            sts32(w, hi); sts32(w + 128, lo);
            split_pack(u1.x, -u1.y, hi, lo);
            sts32(w + BST * 2, hi); sts32(w + BST * 2 + 128, lo);
            u0 = cmul(u0, r2); u1 = cmul(u1, r2);
            w += 2 * BST * 2;
        }
    }
    __syncthreads();   // only B crosses warps

    // ---- A march (warp-local): V[k] = R^k, rows k in [32*wid, 32*wid+32) ----
    {
        float2 R2  = cmul(R, R),   R4  = cmul(R2, R2);
        float2 R8  = cmul(R4, R4), R16 = cmul(R8, R8);
        float2 R32 = cmul(R16, R16), R64 = cmul(R32, R32);
        float2 v0 = make_float2(1.0f, 0.0f);
        if (wid & 1) v0 = R32;
        if (wid & 2) v0 = cmul(v0, R64);
        float2 v1 = cmul(v0, R);
        uint32_t w = smem_u32(sA) + (32 * wid) * (AST * 2) + 4 * lane;
        #pragma unroll
        for (int it = 0; it < 16; ++it) {
            uint32_t hi, lo;
            split_pack(v0.x, v0.y, hi, lo);
            sts32(w, hi); sts32(w + 128, lo);
            split_pack(v1.x, v1.y, hi, lo);
            sts32(w + AST * 2, hi); sts32(w + AST * 2 + 128, lo);
            v0 = cmul(v0, R2); v1 = cmul(v1, R2);
            w += 2 * AST * 2;
        }
    }
    __syncwarp();      // A tile is produced & consumed by this warp only

    // ---- per-lane ldmatrix base addresses ----
    const uint32_t sA_a = smem_u32(sA), sB_a = smem_u32(sB);
    uint32_t aAddr[2], bAddr[2];
    {
        int arow = 32 * wid + (lane & 15);
        uint32_t achk = (lane >> 4) * 16;
        aAddr[0] = sA_a + arow * (AST * 2) + achk;
        aAddr[1] = aAddr[0] + 16 * (AST * 2);
        int brow = 8 * (lane >> 4) + (lane & 7);
        uint32_t bchk = ((lane >> 3) & 1) * 16;
        bAddr[0] = sB_a + brow * (BST * 2) + bchk;
        bAddr[1] = bAddr[0] + 16 * (BST * 2);
    }

    // ---- mma: warp wid computes D rows [32*wid, 32*wid+32) ----
    float acc[2][4][4];
    #pragma unroll
    for (int mt = 0; mt < 2; ++mt)
        #pragma unroll
        for (int nt = 0; nt < 4; ++nt)
            #pragma unroll
            for (int e = 0; e < 4; ++e) acc[mt][nt][e] = 0.0f;

    // per chunk q: load ah, bh once; t0 = ah*bh, t1 = ah*bl, t2 = al*bh
    #pragma unroll
    for (int q = 0; q < 4; ++q) {
        const uint32_t qo = 32u * q;
        uint32_t ah[2][4], bh[2][4];
        ldsm4(ah[0], aAddr[0] + qo);
        ldsm4(ah[1], aAddr[1] + qo);
        ldsm4(bh[0], bAddr[0] + qo);
        ldsm4(bh[1], bAddr[1] + qo);
        // t0: ah * bh
        #pragma unroll
        for (int mt = 0; mt < 2; ++mt)
            #pragma unroll
            for (int nt = 0; nt < 4; ++nt)
                mma16816(acc[mt][nt], ah[mt],
                         bh[nt >> 1][(nt & 1) * 2], bh[nt >> 1][(nt & 1) * 2 + 1]);
        // t1: ah * bl
        {
            uint32_t bl[2][4];
            ldsm4(bl[0], bAddr[0] + 128u + qo);
            ldsm4(bl[1], bAddr[1] + 128u + qo);
            #pragma unroll
            for (int mt = 0; mt < 2; ++mt)
                #pragma unroll
                for (int nt = 0; nt < 4; ++nt)
                    mma16816(acc[mt][nt], ah[mt],
                             bl[nt >> 1][(nt & 1) * 2], bl[nt >> 1][(nt & 1) * 2 + 1]);
        }
        // t2: al * bh
        {
            uint32_t al[2][4];
            ldsm4(al[0], aAddr[0] + 128u + qo);
            ldsm4(al[1], aAddr[1] + 128u + qo);
            #pragma unroll
            for (int mt = 0; mt < 2; ++mt)
                #pragma unroll
                for (int nt = 0; nt < 4; ++nt)
                    mma16816(acc[mt][nt], al[mt],
                             bh[nt >> 1][(nt & 1) * 2], bh[nt >> 1][(nt & 1) * 2 + 1]);
        }
    }

    // ---- store D from fragments: out[h*4096 + row*32 + col] ----
    const int g  = lane >> 2;
    const int tg = lane & 3;
    float* const ob = out + (size_t)h * 4096;
    #pragma unroll
    for (int mt = 0; mt < 2; ++mt) {
        const int row = 32 * wid + 16 * mt + g;
        #pragma unroll
        for (int nt = 0; nt < 4; ++nt) {
            float* p = ob + row * 32 + 8 * nt + 2 * tg;
            *(float2*)p            = make_float2(acc[mt][nt][0], acc[mt][nt][1]);
            *(float2*)(p + 8 * 32) = make_float2(acc[mt][nt][2], acc[mt][nt][3]);
        }
    }
}

// ---------------- launch ----------------------------------------------------
extern "C" void kernel_launch(void* const* d_in, const int* in_sizes, int n_in,
                              void* d_out, int out_size) {
    const float* C      = (const float*)d_in[0];
    const float* log_dt = (const float*)d_in[1];
    const float* lAr    = (const float*)d_in[2];
    const float* Ai     = (const float*)d_in[3];
    const int H = in_sizes[1];               // 1024

    s4d_mma<<<H, 128>>>((float*)d_out, C, log_dt, lAr, Ai);
}

// round 12
// speedup vs baseline: 1.0201x; 1.0201x over previous
#include <cuda_runtime.h>
#include <cuda_bf16.h>
#include <cstdint>
#include <math.h>

// S4D as 1024 batched small GEMMs on mma.sync (HMMA, sm_80 baseline).
//
// K[h, 64k+j] = Re( sum_n cc_n * (r_n^64)^k * r_n^j ),  r_n = exp(dtA[h,n]).
// Per head:  D[64x64] = A[64 x 128] * B[64 x 128]^T   (bf16, fp32 accum)
//   A[k, 2n+0/1] = (Vr_hi, Vi_hi),  A[k, 64+2n+0/1] = (Vr_lo, Vi_lo),  V = r^(64k)
//   B[j, 2n+0/1] = (Ur_hi, -Ui_hi), B[j, 64+2n+0/1] = (Ur_lo, -Ui_lo), U = cc*r^j
// D = Ahi*Bhi + Ahi*Blo + Alo*Bhi (lo*lo dropped ~2^-18): 12 k16 MMA steps.
//
// R12: square tiling (64x64 instead of 128x32) -> smem 44KB->34KB (6 CTAs/SM,
// 24 warps), march rows 160->128 per CTA, waves 1.38->1.15. Warp wid owns
// D k-rows [16wid,16wid+16) -> A march stays warp-local; B crosses warps.

#define AST 136   // row stride in halves (272B; LDSM conflict-free)
#define BST 136

__device__ __forceinline__ float2 cmul(float2 a, float2 b) {
    return make_float2(fmaf(a.x, b.x, -a.y * b.y), fmaf(a.x, b.y, a.y * b.x));
}
// hi = {bf16rn(x), bf16rn(y)}; lo = packed exact residuals
__device__ __forceinline__ void split_pack(float x, float y, uint32_t& hi, uint32_t& lo) {
    asm("cvt.rn.bf16x2.f32 %0, %1, %2;" : "=r"(hi) : "f"(y), "f"(x));
    uint32_t xh, yh;
    asm("prmt.b32 %0, %1, %2, 0x1054;" : "=r"(xh) : "r"(hi), "r"(0));
    asm("prmt.b32 %0, %1, %2, 0x3254;" : "=r"(yh) : "r"(hi), "r"(0));
    float xr = x - __uint_as_float(xh);
    float yr = y - __uint_as_float(yh);
    asm("cvt.rn.bf16x2.f32 %0, %1, %2;" : "=r"(lo) : "f"(yr), "f"(xr));
}
__device__ __forceinline__ uint32_t smem_u32(const void* p) {
    uint32_t a;
    asm("{ .reg .u64 t; cvta.to.shared.u64 t, %1; cvt.u32.u64 %0, t; }" : "=r"(a) : "l"(p));
    return a;
}
__device__ __forceinline__ void sts32(uint32_t addr, uint32_t v) {
    asm volatile("st.shared.b32 [%0], %1;" :: "r"(addr), "r"(v) : "memory");
}
__device__ __forceinline__ void ldsm4(uint32_t* r, uint32_t addr) {
    asm volatile("ldmatrix.sync.aligned.m8n8.x4.shared.b16 {%0,%1,%2,%3}, [%4];"
                 : "=r"(r[0]), "=r"(r[1]), "=r"(r[2]), "=r"(r[3]) : "r"(addr));
}
__device__ __forceinline__ void mma16816(float* c, const uint32_t* a,
                                         uint32_t b0, uint32_t b1) {
    asm("mma.sync.aligned.m16n8k16.row.col.f32.bf16.bf16.f32 "
        "{%0,%1,%2,%3}, {%4,%5,%6,%7}, {%8,%9}, {%0,%1,%2,%3};"
        : "+f"(c[0]), "+f"(c[1]), "+f"(c[2]), "+f"(c[3])
        : "r"(a[0]), "r"(a[1]), "r"(a[2]), "r"(a[3]), "r"(b0), "r"(b1));
}

__global__ void __launch_bounds__(128, 6)
s4d_mma(float* __restrict__ out,
        const float* __restrict__ C, const float* __restrict__ log_dt,
        const float* __restrict__ lAr, const float* __restrict__ Ai) {
    __shared__ __align__(16) __nv_bfloat16 sA[64 * AST];  // 17408 B
    __shared__ __align__(16) __nv_bfloat16 sB[64 * BST];  // 17408 B

    const int h    = blockIdx.x;
    const int wid  = threadIdx.x >> 5;   // warp: A rows / D k-rows [16wid,16wid+16)
    const int lane = threadIdx.x & 31;   // lane == mode n

    // ---- per-thread constants for mode n = lane (dup across warps) ----
    const int idx = h * 32 + lane;
    float dt = expf(log_dt[h]);
    float ar = -expf(lAr[idx]);
    float ai = Ai[idx];
    float x  = ar * dt, th = ai * dt;
    float sy, cy; sincosf(th, &sy, &cy);
    float ex = expf(x);
    float2 r = make_float2(ex * cy, ex * sy);
    float den  = ar * ar + ai * ai;
    float c2   = 2.0f * C[idx] / den;
    float2 cc  = make_float2(c2 * ((r.x - 1.0f) * ar + r.y * ai),
                             c2 * (r.y * ar - (r.x - 1.0f) * ai));

    // power ladder
    float2 r2  = cmul(r, r),   r4  = cmul(r2, r2);
    float2 r8  = cmul(r4, r4), r16 = cmul(r8, r8);
    float2 r32 = cmul(r16, r16);
    float2 R   = cmul(r32, r32);                 // r^64

    // ---- B march: U[j] = cc * r^j, rows j in [16*wid, 16*wid+16) ----
    {
        float2 u0 = cc;
        if (wid & 1) u0 = cmul(u0, r16);
        if (wid & 2) u0 = cmul(u0, r32);
        float2 u1 = cmul(u0, r);
        uint32_t w = smem_u32(sB) + (16 * wid) * (BST * 2) + 4 * lane;
        #pragma unroll
        for (int it = 0; it < 8; ++it) {
            uint32_t hi, lo;
            split_pack(u0.x, -u0.y, hi, lo);
            sts32(w, hi); sts32(w + 128, lo);
            split_pack(u1.x, -u1.y, hi, lo);
            sts32(w + BST * 2, hi); sts32(w + BST * 2 + 128, lo);
            u0 = cmul(u0, r2); u1 = cmul(u1, r2);
            w += 2 * BST * 2;
        }
    }
    __syncthreads();   // only B crosses warps

    // ---- A march (warp-local): V[k] = R^k, rows k in [16*wid, 16*wid+16) ----
    {
        float2 R2  = cmul(R, R),   R4  = cmul(R2, R2);
        float2 R8  = cmul(R4, R4), R16 = cmul(R8, R8);
        float2 v0 = make_float2(1.0f, 0.0f);
        if (wid & 1) v0 = R16;
        if (wid & 2) {
            float2 R32 = cmul(R16, R16);
            v0 = cmul(v0, R32);
        }
        float2 v1 = cmul(v0, R);
        uint32_t w = smem_u32(sA) + (16 * wid) * (AST * 2) + 4 * lane;
        #pragma unroll
        for (int it = 0; it < 8; ++it) {
            uint32_t hi, lo;
            split_pack(v0.x, v0.y, hi, lo);
            sts32(w, hi); sts32(w + 128, lo);
            split_pack(v1.x, v1.y, hi, lo);
            sts32(w + AST * 2, hi); sts32(w + AST * 2 + 128, lo);
            v0 = cmul(v0, R2); v1 = cmul(v1, R2);
            w += 2 * AST * 2;
        }
    }
    __syncwarp();      // A tile produced & consumed by this warp only

    // ---- per-lane ldmatrix base addresses ----
    const uint32_t sA_a = smem_u32(sA), sB_a = smem_u32(sB);
    // A m-tile (16 rows): lanes 0-15 rows 16wid+(lane&15) chk0; 16-31 +16B
    const uint32_t aAddr = sA_a + (16 * wid + (lane & 15)) * (AST * 2)
                         + (lane >> 4) * 16;
    // B n-tile pair p (rows 16p..16p+16): standard x4 pattern
    const uint32_t bAddr0 = sB_a + (8 * (lane >> 4) + (lane & 7)) * (BST * 2)
                          + ((lane >> 3) & 1) * 16;

    // ---- mma: warp wid computes D k-rows [16wid,16wid+16) x 64 j-cols ----
    float acc[8][4];
    #pragma unroll
    for (int nt = 0; nt < 8; ++nt)
        #pragma unroll
        for (int e = 0; e < 4; ++e) acc[nt][e] = 0.0f;

    #pragma unroll
    for (int q = 0; q < 4; ++q) {
        const uint32_t qo = 32u * q;
        uint32_t ah[4], bh[4][4];
        ldsm4(ah, aAddr + qo);
        #pragma unroll
        for (int p = 0; p < 4; ++p)
            ldsm4(bh[p], bAddr0 + p * 16 * (BST * 2) + qo);
        // t0: ah * bh
        #pragma unroll
        for (int nt = 0; nt < 8; ++nt)
            mma16816(acc[nt], ah, bh[nt >> 1][(nt & 1) * 2], bh[nt >> 1][(nt & 1) * 2 + 1]);
        // t1: ah * bl (two 8-reg halves to limit pressure)
        #pragma unroll
        for (int ph = 0; ph < 2; ++ph) {
            uint32_t bl[2][4];
            ldsm4(bl[0], bAddr0 + (2 * ph)     * 16 * (BST * 2) + 128u + qo);
            ldsm4(bl[1], bAddr0 + (2 * ph + 1) * 16 * (BST * 2) + 128u + qo);
            #pragma unroll
            for (int nt = 4 * ph; nt < 4 * ph + 4; ++nt)
                mma16816(acc[nt], ah,
                         bl[(nt >> 1) & 1][(nt & 1) * 2], bl[(nt >> 1) & 1][(nt & 1) * 2 + 1]);
        }
        // t2: al * bh
        {
            uint32_t al[4];
            ldsm4(al, aAddr + 128u + qo);
            #pragma unroll
            for (int nt = 0; nt < 8; ++nt)
                mma16816(acc[nt], al, bh[nt >> 1][(nt & 1) * 2], bh[nt >> 1][(nt & 1) * 2 + 1]);
        }
    }

    // ---- store D: out[h*4096 + k*64 + j], k = 16wid+g(+8), j = 8nt+2tg ----
    const int g  = lane >> 2;
    const int tg = lane & 3;
    float* const ob = out + (size_t)h * 4096 + (16 * wid + g) * 64 + 2 * tg;
    #pragma unroll
    for (int nt = 0; nt < 8; ++nt) {
        float* p = ob + 8 * nt;
        *(float2*)p            = make_float2(acc[nt][0], acc[nt][1]);
        *(float2*)(p + 8 * 64) = make_float2(acc[nt][2], acc[nt][3]);
    }
}

// ---------------- launch ----------------------------------------------------
extern "C" void kernel_launch(void* const* d_in, const int* in_sizes, int n_in,
                              void* d_out, int out_size) {
    const float* C      = (const float*)d_in[0];
    const float* log_dt = (const float*)d_in[1];
    const float* lAr    = (const float*)d_in[2];
    const float* Ai     = (const float*)d_in[3];
    const int H = in_sizes[1];               // 1024

    s4d_mma<<<H, 128>>>((float*)d_out, C, log_dt, lAr, Ai);
}